// round 8
// baseline (speedup 1.0000x reference)
#include <cuda_runtime.h>
#include <cuda_fp16.h>
#include <cstdint>
#include <math.h>

#define BB 2
#define NN 2048
#define CC 1024
#define HH 16
#define DD 64
#define E3 3072
#define MM (BB*NN)   // 4096
#define BH (BB*HH)   // 32

// ---------------- scratch (no allocations allowed) ----------------
__device__ float g_q [BH * NN * DD];
__device__ float g_k [BH * NN * DD];
__device__ float g_v [BH * NN * DD];
__device__ float g_ao[MM * CC];

__device__ __forceinline__ uint32_t smem_u32(const void* p) {
    uint32_t a;
    asm("{ .reg .u64 t; cvta.to.shared.u64 t, %1; cvt.u32.u64 %0, t; }" : "=r"(a) : "l"(p));
    return a;
}
__device__ __forceinline__ void mma16816(float* c, const uint32_t* a, const uint32_t* b) {
    asm volatile("mma.sync.aligned.m16n8k16.row.col.f32.f16.f16.f32 "
        "{%0,%1,%2,%3}, {%4,%5,%6,%7}, {%8,%9}, {%0,%1,%2,%3};"
        : "+f"(c[0]), "+f"(c[1]), "+f"(c[2]), "+f"(c[3])
        : "r"(a[0]), "r"(a[1]), "r"(a[2]), "r"(a[3]), "r"(b[0]), "r"(b[1]));
}
__device__ __forceinline__ void ldsm_x4(uint32_t* r, uint32_t addr) {
    asm volatile("ldmatrix.sync.aligned.m8n8.x4.shared.b16 {%0,%1,%2,%3}, [%4];"
        : "=r"(r[0]), "=r"(r[1]), "=r"(r[2]), "=r"(r[3]) : "r"(addr));
}
__device__ __forceinline__ void ldsm_x2(uint32_t* r, uint32_t addr) {
    asm volatile("ldmatrix.sync.aligned.m8n8.x2.shared.b16 {%0,%1}, [%2];"
        : "=r"(r[0]), "=r"(r[1]) : "r"(addr));
}
__device__ __forceinline__ void ldsm_x2t(uint32_t* r, uint32_t addr) {
    asm volatile("ldmatrix.sync.aligned.m8n8.x2.trans.shared.b16 {%0,%1}, [%2];"
        : "=r"(r[0]), "=r"(r[1]) : "r"(addr));
}
__device__ __forceinline__ uint32_t packh2(__half a, __half b) {
    __half2 t = __halves2half2(a, b);
    return *reinterpret_cast<uint32_t*>(&t);
}
// fp32x4 -> (hi half2x2, lo half2x2)
__device__ __forceinline__ void cvt_split(float4 v, uint2& h, uint2& l) {
    __half h0 = __float2half_rn(v.x), h1 = __float2half_rn(v.y);
    __half h2 = __float2half_rn(v.z), h3 = __float2half_rn(v.w);
    h.x = packh2(h0, h1); h.y = packh2(h2, h3);
    l.x = packh2(__float2half_rn(v.x - __half2float(h0)),
                 __float2half_rn(v.y - __half2float(h1)));
    l.y = packh2(__float2half_rn(v.z - __half2float(h2)),
                 __float2half_rn(v.w - __half2float(h3)));
}

// ---------------- mma.sync fp16-split GEMM, double-buffered, inline split --------
// D[m=token][n=feature] = sum_k A[m][k]*B[n][k], products AhBh+AhBl+AlBh.
// Tile 128x128, BK=32, 512 threads = 16 warps (4x4), warp tile 32x32.
// Dynamic smem: 2 stages x (Ah|Al|Bh|Bl)[128][40] halves = 81920 B.
// MODE 0: A = x, B = W_qkv, scatter to g_q/g_k/g_v.  MODE 1: A = g_ao, B = W_out, +bias.
#define GSMEM 81920
template<int MODE>
__global__ __launch_bounds__(512) void tc_gemm(const float* __restrict__ Ain,
                                               const float* __restrict__ Bin,
                                               const float* __restrict__ bias,
                                               float* __restrict__ outp)
{
    extern __shared__ __half sm[];
    const int tid  = threadIdx.x;
    const int lane = tid & 31;
    const int wid  = tid >> 5;
    const int wm   = wid >> 2;
    const int wn   = wid & 3;
    const int m0 = blockIdx.y * 128;  // token tile
    const int n0 = blockIdx.x * 128;  // feature tile

    const float* pA = (MODE == 0) ? Ain : g_ao;
    const float* pB = Bin;

    const uint32_t sbase = smem_u32(sm);
    const uint32_t a_row = wm * 32 + (lane & 15);
    const uint32_t a_kg  = (lane >> 4) << 3;
    const uint32_t b_kg  = ((lane >> 3) & 1) << 3;

    float acc[2][4][4];
#pragma unroll
    for (int i = 0; i < 2; i++)
#pragma unroll
        for (int j = 0; j < 4; j++)
#pragma unroll
            for (int c = 0; c < 4; c++) acc[i][j][c] = 0.0f;

    // global slots: 1024 float4 per matrix per 32-chunk; 2 per thread
    float4 ra[2], rb[2];
#pragma unroll
    for (int i = 0; i < 2; i++) {
        int slot = tid + i * 512;
        int row = slot >> 3, c4 = (slot & 7) * 4;
        ra[i] = *(const float4*)&pA[(size_t)(m0 + row) * CC + c4];
        rb[i] = *(const float4*)&pB[(size_t)(n0 + row) * CC + c4];
    }

    // store chunk into stage st (half-index offsets: Ah 0, Al 5120, Bh 10240, Bl 15360)
    auto store_chunk = [&](int st) {
#pragma unroll
        for (int i = 0; i < 2; i++) {
            int slot = tid + i * 512;
            int row = slot >> 3, c = (slot & 7) * 4;
            uint2 h, l;
            cvt_split(ra[i], h, l);
            *(uint2*)&sm[st * 20480 +         row * 40 + c] = h;
            *(uint2*)&sm[st * 20480 +  5120 + row * 40 + c] = l;
            cvt_split(rb[i], h, l);
            *(uint2*)&sm[st * 20480 + 10240 + row * 40 + c] = h;
            *(uint2*)&sm[st * 20480 + 15360 + row * 40 + c] = l;
        }
    };

    store_chunk(0);
    __syncthreads();

    for (int k0 = 0; k0 < CC; k0 += 32) {
        const int st = (k0 >> 5) & 1;
        if (k0 + 32 < CC) {
#pragma unroll
            for (int i = 0; i < 2; i++) {
                int slot = tid + i * 512;
                int row = slot >> 3, c4 = (slot & 7) * 4;
                ra[i] = *(const float4*)&pA[(size_t)(m0 + row) * CC + k0 + 32 + c4];
                rb[i] = *(const float4*)&pB[(size_t)(n0 + row) * CC + k0 + 32 + c4];
            }
        }

        const uint32_t base = sbase + st * 40960;   // bytes
#pragma unroll
        for (int ks = 0; ks < 2; ks++) {
            const uint32_t kcol = ks * 16;
            uint32_t ah[2][4], al[2][4];
#pragma unroll
            for (int mt = 0; mt < 2; mt++) {
                uint32_t off = ((a_row + mt * 16) * 40 + kcol + a_kg) * 2;
                ldsm_x4(ah[mt], base + off);
                ldsm_x4(al[mt], base + 10240 + off);
            }
#pragma unroll
            for (int nt = 0; nt < 4; nt++) {
                uint32_t boff = ((wn * 32 + nt * 8 + (lane & 7)) * 40 + kcol + b_kg) * 2;
                uint32_t bhr[2], blr[2];
                ldsm_x2(bhr, base + 20480 + boff);
                ldsm_x2(blr, base + 30720 + boff);
#pragma unroll
                for (int mt = 0; mt < 2; mt++) {
                    mma16816(acc[mt][nt], ah[mt], bhr);
                    mma16816(acc[mt][nt], ah[mt], blr);
                    mma16816(acc[mt][nt], al[mt], bhr);
                }
            }
        }

        if (k0 + 32 < CC) store_chunk(st ^ 1);
        __syncthreads();
    }

    // Epilogue
#pragma unroll
    for (int mt = 0; mt < 2; mt++) {
#pragma unroll
        for (int nt = 0; nt < 4; nt++) {
            const float* c = acc[mt][nt];
            const int col = n0 + wn * 32 + nt * 8 + (lane & 3) * 2;
#pragma unroll
            for (int hr = 0; hr < 2; hr++) {
                const int row = m0 + wm * 32 + mt * 16 + (lane >> 2) + hr * 8;
                float2 val = make_float2(c[hr * 2 + 0], c[hr * 2 + 1]);
                if (MODE == 0) {
                    const int part = col >> 10, rr = col & 1023;
                    const int h = rr >> 6, d = rr & 63;
                    float* dst = (part == 0) ? g_q : (part == 1) ? g_k : g_v;
                    const int b = row >> 11, n = row & 2047;
                    *(float2*)&dst[((size_t)(b * HH + h) * NN + n) * DD + d] = val;
                } else {
                    val.x += bias[col];
                    val.y += bias[col + 1];
                    *(float2*)&outp[(size_t)row * CC + col] = val;
                }
            }
        }
    }
}

// ---------------- MMA flash attention (unchanged from R6) ----------------
#define KVS 72
__global__ __launch_bounds__(256) void attn_mma_kernel()
{
    const int bh   = blockIdx.y;
    const int q0   = blockIdx.x * 128;
    const int tid  = threadIdx.x;
    const int lane = tid & 31;
    const int warp = tid >> 5;

    const float* Qp = g_q + (size_t)bh * NN * DD;
    const float* Kp = g_k + (size_t)bh * NN * DD;
    const float* Vp = g_v + (size_t)bh * NN * DD;

    __shared__ __align__(16) __half smh[18432];
    __half* Qh = smh;          __half* Ql = smh + 9216;
    __half* Kh = smh;          __half* Kl = smh + 4608;
    __half* Vh = smh + 9216;   __half* Vl = smh + 13824;
    const uint32_t sQh = smem_u32(Qh), sQl = smem_u32(Ql);
    const uint32_t sKh = smem_u32(Kh), sKl = smem_u32(Kl);
    const uint32_t sVh = smem_u32(Vh), sVl = smem_u32(Vl);

#pragma unroll
    for (int i = 0; i < 8; i++) {
        int idx = tid + i * 256;
        int row = idx >> 4, c4 = (idx & 15) * 4;
        float4 v = *(const float4*)&Qp[(size_t)(q0 + row) * DD + c4];
        uint2 h, l;
        cvt_split(v, h, l);
        *(uint2*)&Qh[row * KVS + c4] = h;
        *(uint2*)&Ql[row * KVS + c4] = l;
    }
    __syncthreads();

    uint32_t qh[4][4], ql[4][4];
    {
        const uint32_t arow = warp * 16 + (lane & 15);
        const uint32_t akg  = ((lane >> 4) & 1) * 8;
#pragma unroll
        for (int ks = 0; ks < 4; ks++) {
            uint32_t off = (arow * KVS + ks * 16 + akg) * 2;
            ldsm_x4(qh[ks], sQh + off);
            ldsm_x4(ql[ks], sQl + off);
        }
    }
    __syncthreads();

    float O[8][4];
#pragma unroll
    for (int n = 0; n < 8; n++)
#pragma unroll
        for (int c = 0; c < 4; c++) O[n][c] = 0.0f;
    float m0r = -1e30f, m1r = -1e30f;
    float l0 = 0.0f, l1 = 0.0f;

    const uint32_t bkey = (lane & 7);
    const uint32_t bkg  = ((lane >> 3) & 1) * 8;
    const uint32_t vrow = (lane & 15);

    for (int j0 = 0; j0 < NN; j0 += 64) {
#pragma unroll
        for (int i = 0; i < 4; i++) {
            int idx = tid + i * 256;
            int row = idx >> 4, c4 = (idx & 15) * 4;
            float4 kv = *(const float4*)&Kp[(size_t)(j0 + row) * DD + c4];
            float4 vv = *(const float4*)&Vp[(size_t)(j0 + row) * DD + c4];
            uint2 h, l;
            cvt_split(kv, h, l);
            *(uint2*)&Kh[row * KVS + c4] = h;
            *(uint2*)&Kl[row * KVS + c4] = l;
            cvt_split(vv, h, l);
            *(uint2*)&Vh[row * KVS + c4] = h;
            *(uint2*)&Vl[row * KVS + c4] = l;
        }
        __syncthreads();

        float s[8][4];
#pragma unroll
        for (int n = 0; n < 8; n++)
#pragma unroll
            for (int c = 0; c < 4; c++) s[n][c] = 0.0f;

#pragma unroll
        for (int ks = 0; ks < 4; ks++) {
#pragma unroll
            for (int nt = 0; nt < 8; nt++) {
                uint32_t boff = ((nt * 8 + bkey) * KVS + ks * 16 + bkg) * 2;
                uint32_t kbh[2], kbl[2];
                ldsm_x2(kbh, sKh + boff);
                ldsm_x2(kbl, sKl + boff);
                mma16816(s[nt], qh[ks], kbh);
                mma16816(s[nt], qh[ks], kbl);
                mma16816(s[nt], ql[ks], kbh);
            }
        }

        float mloc0 = -1e30f, mloc1 = -1e30f;
#pragma unroll
        for (int nt = 0; nt < 8; nt++) {
#pragma unroll
            for (int c = 0; c < 4; c++) s[nt][c] *= 0.125f;
            mloc0 = fmaxf(mloc0, fmaxf(s[nt][0], s[nt][1]));
            mloc1 = fmaxf(mloc1, fmaxf(s[nt][2], s[nt][3]));
        }
        mloc0 = fmaxf(mloc0, __shfl_xor_sync(0xffffffffu, mloc0, 1));
        mloc0 = fmaxf(mloc0, __shfl_xor_sync(0xffffffffu, mloc0, 2));
        mloc1 = fmaxf(mloc1, __shfl_xor_sync(0xffffffffu, mloc1, 1));
        mloc1 = fmaxf(mloc1, __shfl_xor_sync(0xffffffffu, mloc1, 2));

        float mn0 = fmaxf(m0r, mloc0), mn1 = fmaxf(m1r, mloc1);
        float cr0 = __expf(m0r - mn0), cr1 = __expf(m1r - mn1);
        m0r = mn0; m1r = mn1;
        l0 *= cr0; l1 *= cr1;
#pragma unroll
        for (int n = 0; n < 8; n++) {
            O[n][0] *= cr0; O[n][1] *= cr0;
            O[n][2] *= cr1; O[n][3] *= cr1;
        }

        float ls0 = 0.0f, ls1 = 0.0f;
        uint32_t aPh[4][4], aPl[4][4];
#pragma unroll
        for (int nt = 0; nt < 8; nt++) {
            float p0 = __expf(s[nt][0] - m0r);
            float p1 = __expf(s[nt][1] - m0r);
            float p2 = __expf(s[nt][2] - m1r);
            float p3 = __expf(s[nt][3] - m1r);
            ls0 += p0 + p1; ls1 += p2 + p3;
            __half h0 = __float2half_rn(p0), h1 = __float2half_rn(p1);
            __half h2 = __float2half_rn(p2), h3 = __float2half_rn(p3);
            const int kt = nt >> 1, hi2 = (nt & 1) * 2;
            aPh[kt][hi2 + 0] = packh2(h0, h1);
            aPh[kt][hi2 + 1] = packh2(h2, h3);
            aPl[kt][hi2 + 0] = packh2(__float2half_rn(p0 - __half2float(h0)),
                                      __float2half_rn(p1 - __half2float(h1)));
            aPl[kt][hi2 + 1] = packh2(__float2half_rn(p2 - __half2float(h2)),
                                      __float2half_rn(p3 - __half2float(h3)));
        }
        ls0 += __shfl_xor_sync(0xffffffffu, ls0, 1);
        ls0 += __shfl_xor_sync(0xffffffffu, ls0, 2);
        ls1 += __shfl_xor_sync(0xffffffffu, ls1, 1);
        ls1 += __shfl_xor_sync(0xffffffffu, ls1, 2);
        l0 += ls0; l1 += ls1;

#pragma unroll
        for (int kt = 0; kt < 4; kt++) {
#pragma unroll
            for (int nd = 0; nd < 8; nd++) {
                uint32_t voff = ((kt * 16 + vrow) * KVS + nd * 8) * 2;
                uint32_t vbh[2], vbl[2];
                ldsm_x2t(vbh, sVh + voff);
                ldsm_x2t(vbl, sVl + voff);
                mma16816(O[nd], aPh[kt], vbh);
                mma16816(O[nd], aPh[kt], vbl);
                mma16816(O[nd], aPl[kt], vbh);
            }
        }
        __syncthreads();
    }

    const float inv0 = 1.0f / l0, inv1 = 1.0f / l1;
    const int b = bh >> 4, h = bh & 15;
    const int row0 = q0 + warp * 16 + (lane >> 2);
    const int row1 = row0 + 8;
#pragma unroll
    for (int nd = 0; nd < 8; nd++) {
        const int d = nd * 8 + (lane & 3) * 2;
        *(float2*)&g_ao[((size_t)(b * NN + row0)) * CC + h * DD + d] =
            make_float2(O[nd][0] * inv0, O[nd][1] * inv0);
        *(float2*)&g_ao[((size_t)(b * NN + row1)) * CC + h * DD + d] =
            make_float2(O[nd][2] * inv1, O[nd][3] * inv1);
    }
}

// ---------------------------------------------------------------------------
extern "C" void kernel_launch(void* const* d_in, const int* in_sizes, int n_in,
                              void* d_out, int out_size)
{
    const float* x     = (const float*)d_in[0];
    const float* W_qkv = (const float*)d_in[1];
    const float* W_out = (const float*)d_in[2];
    const float* b_out = (const float*)d_in[3];
    float* out = (float*)d_out;
    (void)in_sizes; (void)n_in; (void)out_size;

    cudaFuncSetAttribute(tc_gemm<0>, cudaFuncAttributeMaxDynamicSharedMemorySize, GSMEM);
    cudaFuncSetAttribute(tc_gemm<1>, cudaFuncAttributeMaxDynamicSharedMemorySize, GSMEM);

    // 1) QKV projection (inline fp16 split), scatter to g_q/g_k/g_v
    {
        dim3 grid(E3 / 128, MM / 128);   // (24, 32)
        tc_gemm<0><<<grid, 512, GSMEM>>>(x, W_qkv, nullptr, nullptr);
    }
    // 2) Flash attention (mma.sync)
    {
        dim3 grid(NN / 128, BH);
        attn_mma_kernel<<<grid, 256>>>();
    }
    // 3) Output projection + bias
    {
        dim3 grid(CC / 128, MM / 128);   // (8, 32)
        tc_gemm<1><<<grid, 512, GSMEM>>>(nullptr, W_out, b_out, out);
    }
}